// round 14
// baseline (speedup 1.0000x reference)
#include <cuda_runtime.h>
#include <cstdint>

// Output: [1024, 201000] fp32 = one_hot(h,1e5) ++ one_hot(r,1e3) ++ one_hot(t,1e5).
// Flattened 1-D store-first kernel with 256-bit stores (st.global.v8.f32,
// sm_100+): TOTAL4 = 51,456,000 float4s = 25125 blocks x 2048 exactly ->
// every block full and branch-free. Each thread issues 2 x 32B zero stores,
// then the owning thread overwrites hot elements with 1.0f (same-thread
// stores to the same address are program-ordered).

static constexpr int BATCH = 1024;
static constexpr int ENTITIES_N = 100000;
static constexpr int RELATIONS_N = 1000;
static constexpr int WIDTH = ENTITIES_N * 2 + RELATIONS_N;   // 201000 floats/row
static constexpr long long TOTAL = (long long)BATCH * WIDTH; // 205,824,000 floats
static constexpr int TOTAL4 = (int)(TOTAL / 4);              // 51,456,000 float4s
static constexpr int THREADS = 512;
static constexpr int F4_PER_THREAD = 4;                      // as 2 x (2 float4) v8 stores
static constexpr int F4_PER_BLOCK = THREADS * F4_PER_THREAD; // 2048
static constexpr int NBLOCKS = TOTAL4 / F4_PER_BLOCK;        // 25125, exact
static_assert(NBLOCKS * F4_PER_BLOCK == TOTAL4, "grid must divide exactly");

__device__ __forceinline__ void stg_v8_zero(float* addr) {
    asm volatile(
        "st.global.cs.v8.f32 [%0], {%1,%1,%1,%1,%1,%1,%1,%1};"
        :: "l"(addr), "f"(0.0f) : "memory");
}

__global__ void __launch_bounds__(THREADS) onehot_kernel(
    float* __restrict__ outf,
    const int* __restrict__ hID,
    const int* __restrict__ rID,
    const int* __restrict__ tID) {

    const int tid = threadIdx.x;
    const int base4 = blockIdx.x * F4_PER_BLOCK;   // global float4 index of block start
    const int lo = base4 * 4;                      // global float range of block
    const int hi = lo + F4_PER_BLOCK * 4;          // 8192 floats (< WIDTH)

    // Each thread owns float4 slots {2*tid, 2*tid+1} and {2*tid + 2*THREADS, +1}:
    // two 32-byte-aligned v8 stores, coalesced across the warp.
    float* s0 = outf + (long long)(base4 + 2 * tid) * 4;

    // ── Phase 1: branch-free dense zero burst (2 x STG.256 per thread) ──
    stg_v8_zero(s0);
    stg_v8_zero(s0 + 2 * THREADS * 4);

    // ── Phase 2: hot-element fixup for the (at most 2) rows this block spans ──
    const int row0 = lo / WIDTH;
    const int row1 = (hi - 1) / WIDTH;

    #pragma unroll 1
    for (int row = row0; row <= row1; row++) {
        const int rs = row * WIDTH;                // row start (global float index)
        const int c0 = rs + __ldg(hID + row);
        const int c1 = rs + ENTITIES_N + __ldg(rID + row);
        const int c2 = rs + ENTITIES_N + RELATIONS_N + __ldg(tID + row);

        #pragma unroll
        for (int j = 0; j < 3; j++) {
            const int c = (j == 0) ? c0 : (j == 1) ? c1 : c2;
            if (c >= lo && c < hi) {
                const int pos4 = (c >> 2) - base4;       // float4 slot within block
                // layout: slot = seg*2*THREADS + 2*tid + b  ->  owner tid = (slot/2) % THREADS
                if (((pos4 >> 1) & (THREADS - 1)) == tid) {
                    outf[c] = 1.0f;                      // ordered after own zero store
                }
            }
        }
    }
}

extern "C" void kernel_launch(void* const* d_in, const int* in_sizes, int n_in,
                              void* d_out, int out_size) {
    // inputs: z (float32, unused), hID (int32), rID (int32), tID (int32)
    const int* hID = (const int*)d_in[1];
    const int* rID = (const int*)d_in[2];
    const int* tID = (const int*)d_in[3];

    onehot_kernel<<<NBLOCKS, THREADS>>>((float*)d_out, hID, rID, tID);
}